// round 1
// baseline (speedup 1.0000x reference)
#include <cuda_runtime.h>

#define NB  2
#define SEQ 1024
#define DIM 1024
#define NH  16
#define DK  64
#define FF  4096
#define NL  4
#define MROWS (NB*SEQ)   // 2048

// ---------------- scratch (static device memory; no allocations) -------------
__device__ float g_X  [MROWS*DIM];
__device__ float g_X1 [MROWS*DIM];
__device__ float g_Yb [MROWS*DIM];
__device__ float g_Qb [MROWS*DIM];
__device__ float g_Kb [MROWS*DIM];
__device__ float g_Vb [MROWS*DIM];
__device__ float g_Ob [MROWS*DIM];
__device__ float g_Hid[MROWS*FF];

// ---------------- generic SGEMM: C = A(MxK) @ W(KxN) + bias (+R) (+relu) -----
// headW=1: W is (H, K, 64) per-head blocks; output column n -> head n>>6, k n&63
__global__ __launch_bounds__(256)
void gemm_kernel(const float* __restrict__ A, const float* __restrict__ W,
                 const float* __restrict__ bias, const float* __restrict__ R,
                 float* __restrict__ C, int M, int N, int K, int headW, int relu)
{
    __shared__ float As[8][128];
    __shared__ float Bs[8][128];
    const int tid = threadIdx.x;
    const int tx  = tid & 15, ty = tid >> 4;
    const int m0  = blockIdx.y * 128, n0 = blockIdx.x * 128;

    float acc[8][8];
#pragma unroll
    for (int i = 0; i < 8; i++)
#pragma unroll
        for (int j = 0; j < 8; j++) acc[i][j] = 0.f;

    const int arow = tid >> 1;           // 0..127
    const int acol = (tid & 1) << 2;     // 0 or 4
    const int brow = tid >> 5;           // 0..7
    const int bcol = (tid & 31) << 2;    // 0..124
    const int ncol = n0 + bcol;

    const float* Ap = A + (size_t)(m0 + arow) * K + acol;
    const float* Wp;
    size_t wstep;
    if (headW) {
        Wp = W + (size_t)(ncol >> 6) * ((size_t)K * 64) + (size_t)brow * 64 + (ncol & 63);
        wstep = (size_t)8 * 64;
    } else {
        Wp = W + (size_t)brow * N + ncol;
        wstep = (size_t)8 * N;
    }

    for (int k0 = 0; k0 < K; k0 += 8) {
        float4 av = *(const float4*)(Ap + k0);
        As[acol+0][arow] = av.x; As[acol+1][arow] = av.y;
        As[acol+2][arow] = av.z; As[acol+3][arow] = av.w;
        *(float4*)&Bs[brow][bcol] = *(const float4*)Wp;
        Wp += wstep;
        __syncthreads();
#pragma unroll
        for (int kk = 0; kk < 8; kk++) {
            float4 a0 = *(const float4*)&As[kk][ty*8];
            float4 a1 = *(const float4*)&As[kk][ty*8+4];
            float4 b0 = *(const float4*)&Bs[kk][tx*8];
            float4 b1 = *(const float4*)&Bs[kk][tx*8+4];
            float a[8] = {a0.x,a0.y,a0.z,a0.w,a1.x,a1.y,a1.z,a1.w};
            float b[8] = {b0.x,b0.y,b0.z,b0.w,b1.x,b1.y,b1.z,b1.w};
#pragma unroll
            for (int i = 0; i < 8; i++)
#pragma unroll
                for (int j = 0; j < 8; j++) acc[i][j] += a[i]*b[j];
        }
        __syncthreads();
    }

#pragma unroll
    for (int i = 0; i < 8; i++) {
        const int row = m0 + ty*8 + i;
#pragma unroll
        for (int j = 0; j < 8; j++) {
            const int col = n0 + tx*8 + j;
            float v = acc[i][j] + bias[col];
            if (R)    v += R[(size_t)row*N + col];
            if (relu) v = fmaxf(v, 0.f);
            C[(size_t)row*N + col] = v;
        }
    }
}

// ---------------- fused flash attention (fp32, 64-row Q tile) ----------------
// Q/K/V/O layout: [(b*SEQ + s)*DIM + h*DK + k]
__device__ __forceinline__ int ksw(int r, int c) { return r*64 + (c ^ (r & 31)); }

__global__ __launch_bounds__(256)
void attn_kernel(const float* __restrict__ Qg, const float* __restrict__ Kg,
                 const float* __restrict__ Vg, float* __restrict__ Og,
                 const int* __restrict__ mask_ptr)
{
    __shared__ float Qs[64*64];
    __shared__ float Ks[64*64];   // reused as P after scores
    __shared__ float Vs[64*64];

    const int q0 = blockIdx.x * 64;
    const int h  = blockIdx.y;
    const int b  = blockIdx.z;
    const int tid = threadIdx.x;
    const int tx = tid & 15, ty = tid >> 4;

    const int mask_lim = mask_ptr ? *mask_ptr : SEQ;

    const float* Qb = Qg + (size_t)b*SEQ*DIM + (size_t)h*DK;
    const float* Kb = Kg + (size_t)b*SEQ*DIM + (size_t)h*DK;
    const float* Vb = Vg + (size_t)b*SEQ*DIM + (size_t)h*DK;

    for (int e = tid; e < 4096; e += 256) {
        int r = e >> 6, c = e & 63;
        Qs[r*64+c] = Qb[(size_t)(q0+r)*DIM + c];
    }

    float m_i[4], l_i[4], o[4][4];
#pragma unroll
    for (int i = 0; i < 4; i++) {
        m_i[i] = -1e30f; l_i[i] = 0.f;
#pragma unroll
        for (int j = 0; j < 4; j++) o[i][j] = 0.f;
    }

    for (int t0 = 0; t0 < mask_lim; t0 += 64) {
        __syncthreads();
        for (int e = tid; e < 4096; e += 256) {
            int r = e >> 6, c = e & 63;
            Ks[ksw(r,c)] = Kb[(size_t)(t0+r)*DIM + c];
            Vs[r*64+c]   = Vb[(size_t)(t0+r)*DIM + c];
        }
        __syncthreads();

        float s[4][4];
#pragma unroll
        for (int i = 0; i < 4; i++)
#pragma unroll
            for (int j = 0; j < 4; j++) s[i][j] = 0.f;

        for (int kk = 0; kk < 64; kk++) {
            float qv[4], kv[4];
#pragma unroll
            for (int i = 0; i < 4; i++) qv[i] = Qs[(ty*4+i)*64 + kk];
#pragma unroll
            for (int j = 0; j < 4; j++) kv[j] = Ks[ksw(tx*4+j, kk)];
#pragma unroll
            for (int i = 0; i < 4; i++)
#pragma unroll
                for (int j = 0; j < 4; j++) s[i][j] += qv[i]*kv[j];
        }

#pragma unroll
        for (int i = 0; i < 4; i++) {
            float mt = -1e30f;
#pragma unroll
            for (int j = 0; j < 4; j++) {
                int col = t0 + tx*4 + j;
                float v = s[i][j] * 0.125f;             // 1/sqrt(64)
                if (col >= mask_lim) v = -1e30f;
                s[i][j] = v;
                mt = fmaxf(mt, v);
            }
#pragma unroll
            for (int off = 8; off; off >>= 1)
                mt = fmaxf(mt, __shfl_xor_sync(0xffffffffu, mt, off, 16));
            float mnew = fmaxf(m_i[i], mt);
            float corr = __expf(m_i[i] - mnew);
            l_i[i] *= corr;
#pragma unroll
            for (int j = 0; j < 4; j++) o[i][j] *= corr;
            float rs = 0.f;
#pragma unroll
            for (int j = 0; j < 4; j++) {
                float p = __expf(s[i][j] - mnew);
                s[i][j] = p; rs += p;
            }
#pragma unroll
            for (int off = 8; off; off >>= 1)
                rs += __shfl_xor_sync(0xffffffffu, rs, off, 16);
            l_i[i] += rs; m_i[i] = mnew;
        }

        __syncthreads();                    // done reading Ks
#pragma unroll
        for (int i = 0; i < 4; i++)
#pragma unroll
            for (int j = 0; j < 4; j++)
                Ks[ksw(ty*4+i, tx*4+j)] = s[i][j];   // P tile into Ks buffer
        __syncthreads();

        for (int t = 0; t < 64; t++) {
            float pv[4], vv[4];
#pragma unroll
            for (int i = 0; i < 4; i++) pv[i] = Ks[ksw(ty*4+i, t)];
#pragma unroll
            for (int j = 0; j < 4; j++) vv[j] = Vs[t*64 + tx*4+j];
#pragma unroll
            for (int i = 0; i < 4; i++)
#pragma unroll
                for (int j = 0; j < 4; j++) o[i][j] += pv[i]*vv[j];
        }
    }

#pragma unroll
    for (int i = 0; i < 4; i++) {
        float inv = 1.f / l_i[i];
        int row = q0 + ty*4 + i;
#pragma unroll
        for (int j = 0; j < 4; j++)
            Og[(size_t)(b*SEQ + row)*DIM + h*DK + tx*4 + j] = o[i][j]*inv;
    }
}

// ---------------- BatchNorm1d over (B,S,D): stats over (b,d) per s ----------
__global__ __launch_bounds__(256)
void bn_kernel(float* __restrict__ X, const float* __restrict__ g,
               const float* __restrict__ be)
{
    const int s = blockIdx.x;
    const int tid = threadIdx.x;
    float v[8];
    float sum = 0.f, sq = 0.f;
#pragma unroll
    for (int r = 0; r < 8; r++) {
        int idx = r*256 + tid;              // 0..2047 over (b,d)
        int b = idx >> 10, d = idx & 1023;
        float x = X[(size_t)(b*SEQ + s)*DIM + d];
        v[r] = x; sum += x; sq += x*x;
    }
#pragma unroll
    for (int off = 16; off; off >>= 1) {
        sum += __shfl_xor_sync(0xffffffffu, sum, off);
        sq  += __shfl_xor_sync(0xffffffffu, sq,  off);
    }
    __shared__ float ssum[8], ssq[8];
    if ((tid & 31) == 0) { ssum[tid>>5] = sum; ssq[tid>>5] = sq; }
    __syncthreads();
    sum = 0.f; sq = 0.f;
#pragma unroll
    for (int w = 0; w < 8; w++) { sum += ssum[w]; sq += ssq[w]; }
    const float mean = sum * (1.f/2048.f);
    const float var  = sq  * (1.f/2048.f) - mean*mean;   // biased, as in reference
    const float inv  = rsqrtf(var + 1e-5f);
    const float sc   = g[s] * inv;
    const float sh   = be[s] - mean * sc;
#pragma unroll
    for (int r = 0; r < 8; r++) {
        int idx = r*256 + tid;
        int b = idx >> 10, d = idx & 1023;
        X[(size_t)(b*SEQ + s)*DIM + d] = v[r]*sc + sh;
    }
}

// ---------------- host orchestration ----------------------------------------
extern "C" void kernel_launch(void* const* d_in, const int* in_sizes, int n_in,
                              void* d_out, int out_size)
{
    const float* x   = (const float*)d_in[0];
    const float* Wq1 = (const float*)d_in[1];
    const float* bq1 = (const float*)d_in[2];
    const float* Wk1 = (const float*)d_in[3];
    const float* bk1 = (const float*)d_in[4];
    const float* Wv1 = (const float*)d_in[5];
    const float* bv1 = (const float*)d_in[6];
    const float* Wo1 = (const float*)d_in[7];
    const float* bo1 = (const float*)d_in[8];
    const float* Wq2 = (const float*)d_in[9];
    const float* bq2 = (const float*)d_in[10];
    const float* Wk2 = (const float*)d_in[11];
    const float* bk2 = (const float*)d_in[12];
    const float* Wv2 = (const float*)d_in[13];
    const float* bv2 = (const float*)d_in[14];
    const float* Wo2 = (const float*)d_in[15];
    const float* bo2 = (const float*)d_in[16];
    const float* g1  = (const float*)d_in[17];
    const float* be1 = (const float*)d_in[18];
    const float* g2  = (const float*)d_in[19];
    const float* be2 = (const float*)d_in[20];
    const float* g3  = (const float*)d_in[21];
    const float* be3 = (const float*)d_in[22];
    const float* W1  = (const float*)d_in[23];
    const float* bf1 = (const float*)d_in[24];
    const float* W2  = (const float*)d_in[25];
    const float* bf2 = (const float*)d_in[26];
    const int*   msk = (const int*)d_in[27];

    float *X, *X1, *Y, *Q, *K, *V, *O, *Hid;
    cudaGetSymbolAddress((void**)&X,  g_X);
    cudaGetSymbolAddress((void**)&X1, g_X1);
    cudaGetSymbolAddress((void**)&Y,  g_Yb);
    cudaGetSymbolAddress((void**)&Q,  g_Qb);
    cudaGetSymbolAddress((void**)&K,  g_Kb);
    cudaGetSymbolAddress((void**)&V,  g_Vb);
    cudaGetSymbolAddress((void**)&O,  g_Ob);
    cudaGetSymbolAddress((void**)&Hid,g_Hid);

    const size_t bytesD = (size_t)MROWS * DIM * sizeof(float);
    cudaMemcpyAsync(X, x, bytesD, cudaMemcpyDeviceToDevice);

    dim3 gD(DIM/128, MROWS/128);   // (8,16)
    dim3 gF(FF/128,  MROWS/128);   // (32,16)
    dim3 gA(SEQ/64, NH, NB);       // (16,16,2)

    for (int l = 0; l < NL; l++) {
        const size_t wO  = (size_t)l * NH * DIM * DK;   // QKV weights
        const size_t bO  = (size_t)l * NH * DK;         // QKV biases
        const size_t woO = (size_t)l * NH * DK * DIM;   // Wo
        const size_t dO  = (size_t)l * DIM;             // bo / g / be / bf2
        const size_t w1O = (size_t)l * DIM * FF;
        const size_t f1O = (size_t)l * FF;
        const size_t w2O = (size_t)l * FF * DIM;

        // ---- masked self-attention ----
        gemm_kernel<<<gD, 256>>>(X, Wq1+wO, bq1+bO, nullptr, Q, MROWS, DIM, DIM, 1, 0);
        gemm_kernel<<<gD, 256>>>(X, Wk1+wO, bk1+bO, nullptr, K, MROWS, DIM, DIM, 1, 0);
        gemm_kernel<<<gD, 256>>>(X, Wv1+wO, bv1+bO, nullptr, V, MROWS, DIM, DIM, 1, 0);
        attn_kernel<<<gA, 256>>>(Q, K, V, O, msk);
        gemm_kernel<<<gD, 256>>>(O, Wo1+woO, bo1+dO, X, X1, MROWS, DIM, DIM, 0, 0);
        bn_kernel<<<SEQ, 256>>>(X1, g1+dO, be1+dO);

        // ---- second (unmasked) self-attention; residual from block input X ----
        gemm_kernel<<<gD, 256>>>(X1, Wq2+wO, bq2+bO, nullptr, Q, MROWS, DIM, DIM, 1, 0);
        gemm_kernel<<<gD, 256>>>(X1, Wk2+wO, bk2+bO, nullptr, K, MROWS, DIM, DIM, 1, 0);
        gemm_kernel<<<gD, 256>>>(X1, Wv2+wO, bv2+bO, nullptr, V, MROWS, DIM, DIM, 1, 0);
        attn_kernel<<<gA, 256>>>(Q, K, V, O, nullptr);
        gemm_kernel<<<gD, 256>>>(O, Wo2+woO, bo2+dO, X, Y, MROWS, DIM, DIM, 0, 0);
        bn_kernel<<<SEQ, 256>>>(Y, g2+dO, be2+dO);

        // ---- FFN; residual from X1 ----
        gemm_kernel<<<gF, 256>>>(Y, W1+w1O, bf1+f1O, nullptr, Hid, MROWS, FF, DIM, 0, 1);
        gemm_kernel<<<gD, 256>>>(Hid, W2+w2O, bf2+dO, X1, X, MROWS, DIM, FF, 0, 0);
        bn_kernel<<<SEQ, 256>>>(X, g3+dO, be3+dO);
    }

    cudaMemcpyAsync(d_out, X, bytesD, cudaMemcpyDeviceToDevice);
}

// round 3
// speedup vs baseline: 2.3166x; 2.3166x over previous
#include <cuda_runtime.h>
#include <cuda_bf16.h>
#include <cstdint>

#define NB  2
#define SEQ 1024
#define DIM 1024
#define NH  16
#define DK  64
#define FF  4096
#define NL  4
#define MROWS (NB*SEQ)   // 2048

// ---------------- PTX helpers (baseline sm_103 — NO arch-feature suffix) -----
__device__ __forceinline__ uint32_t smem_to_u32(const void* p) {
    uint32_t a;
    asm("{ .reg .u64 t; cvta.to.shared.u64 t, %1; cvt.u32.u64 %0, t; }" : "=r"(a) : "l"(p));
    return a;
}
__device__ __forceinline__ void cpasync16(uint32_t dst, const void* src) {
    asm volatile("cp.async.cg.shared.global [%0], [%1], 16;"
                 :: "r"(dst), "l"(__cvta_generic_to_global(src)) : "memory");
}
__device__ __forceinline__ void cpcommit() { asm volatile("cp.async.commit_group;" ::: "memory"); }
__device__ __forceinline__ void cpwait0()  { asm volatile("cp.async.wait_group 0;" ::: "memory"); }

__device__ __forceinline__ void ldsm4(uint32_t& r0, uint32_t& r1, uint32_t& r2, uint32_t& r3,
                                      uint32_t a) {
    asm volatile("ldmatrix.sync.aligned.m8n8.x4.shared.b16 {%0,%1,%2,%3}, [%4];"
                 : "=r"(r0), "=r"(r1), "=r"(r2), "=r"(r3) : "r"(a));
}
__device__ __forceinline__ void mma16816(float* d, const uint32_t* a, const uint32_t* b) {
    asm volatile("mma.sync.aligned.m16n8k16.row.col.f32.bf16.bf16.f32 "
                 "{%0,%1,%2,%3}, {%4,%5,%6,%7}, {%8,%9}, {%0,%1,%2,%3};"
                 : "+f"(d[0]), "+f"(d[1]), "+f"(d[2]), "+f"(d[3])
                 : "r"(a[0]), "r"(a[1]), "r"(a[2]), "r"(a[3]), "r"(b[0]), "r"(b[1]));
}

// ---------------- scratch (static device memory) -----------------------------
__device__ float g_X  [MROWS*DIM];
__device__ float g_X1 [MROWS*DIM];
__device__ float g_Yb [MROWS*DIM];
__device__ float g_Qb [MROWS*DIM];
__device__ float g_Kb [MROWS*DIM];
__device__ float g_Vb [MROWS*DIM];
__device__ float g_Ob [MROWS*DIM];
__device__ float g_Hid[MROWS*FF];
// split-bf16 weights, transposed to [N][K], all layers
__device__ __nv_bfloat16 g_Whi[64u*1024*1024];
__device__ __nv_bfloat16 g_Wlo[64u*1024*1024];
// split-bf16 activations (max 2048x4096)
__device__ __nv_bfloat16 g_Ahi[MROWS*FF];
__device__ __nv_bfloat16 g_Alo[MROWS*FF];

#define LAYER_W  (16u*1024*1024)
#define OFF_Q1   (0u)
#define OFF_K1   (1u*1024*1024)
#define OFF_V1   (2u*1024*1024)
#define OFF_O1   (3u*1024*1024)
#define OFF_Q2   (4u*1024*1024)
#define OFF_K2   (5u*1024*1024)
#define OFF_V2   (6u*1024*1024)
#define OFF_O2   (7u*1024*1024)
#define OFF_W1   (8u*1024*1024)
#define OFF_W2   (12u*1024*1024)

// ---------------- activation split: fp32 -> (hi, lo) bf16 --------------------
__global__ __launch_bounds__(256) void split_f32(const float* __restrict__ x,
        __nv_bfloat16* __restrict__ h, __nv_bfloat16* __restrict__ l, int n4)
{
    int i = blockIdx.x * 256 + threadIdx.x;
    if (i >= n4) return;
    float4 v = ((const float4*)x)[i];
    __nv_bfloat16 h0 = __float2bfloat16(v.x), h1 = __float2bfloat16(v.y);
    __nv_bfloat16 h2 = __float2bfloat16(v.z), h3 = __float2bfloat16(v.w);
    __nv_bfloat16 l0 = __float2bfloat16(v.x - __bfloat162float(h0));
    __nv_bfloat16 l1 = __float2bfloat16(v.y - __bfloat162float(h1));
    __nv_bfloat16 l2 = __float2bfloat16(v.z - __bfloat162float(h2));
    __nv_bfloat16 l3 = __float2bfloat16(v.w - __bfloat162float(h3));
    uint2 hp, lp;
    hp.x = (uint32_t)__bfloat16_as_ushort(h0) | ((uint32_t)__bfloat16_as_ushort(h1) << 16);
    hp.y = (uint32_t)__bfloat16_as_ushort(h2) | ((uint32_t)__bfloat16_as_ushort(h3) << 16);
    lp.x = (uint32_t)__bfloat16_as_ushort(l0) | ((uint32_t)__bfloat16_as_ushort(l1) << 16);
    lp.y = (uint32_t)__bfloat16_as_ushort(l2) | ((uint32_t)__bfloat16_as_ushort(l3) << 16);
    ((uint2*)h)[i] = hp;
    ((uint2*)l)[i] = lp;
}

// ------------- weight transpose+split: W[K,N](or head) -> Wt[N,K] hi/lo ------
__global__ __launch_bounds__(256) void wsplit_t(const float* __restrict__ W,
        __nv_bfloat16* __restrict__ oh, __nv_bfloat16* __restrict__ ol,
        int K, int N, size_t inLayerStride, size_t outOff, int headMode)
{
    __shared__ float t[32][33];
    int tx = threadIdx.x & 31, ty = threadIdx.x >> 5;   // block 256 = 32x8
    int k0 = blockIdx.x * 32, n0 = blockIdx.y * 32;
    const float* Win = W + (size_t)blockIdx.z * inLayerStride;
    size_t ob = (size_t)blockIdx.z * LAYER_W + outOff;
#pragma unroll
    for (int i = 0; i < 4; i++) {
        int k = k0 + ty + 8*i, n = n0 + tx;
        size_t idx = headMode ? ((size_t)(n >> 6) * K * 64 + (size_t)k * 64 + (n & 63))
                              : ((size_t)k * N + n);
        t[ty + 8*i][tx] = Win[idx];
    }
    __syncthreads();
#pragma unroll
    for (int i = 0; i < 4; i++) {
        int n = n0 + ty + 8*i, k = k0 + tx;
        float v = t[tx][ty + 8*i];
        __nv_bfloat16 hi = __float2bfloat16(v);
        oh[ob + (size_t)n * K + k] = hi;
        ol[ob + (size_t)n * K + k] = __float2bfloat16(v - __bfloat162float(hi));
    }
}

// ---------------- split-bf16 HMMA GEMM ---------------------------------------
// C[2048, N] = A[2048, K] @ B^T (B stored [N][K], K-major) + bias (+R) (+relu)
// CTA 128x128, BK=64, 8 warps (2M x 4N), warp tile 64x32, m16n8k16 atoms.
#define RSB 144                       // padded smem row stride (bytes)
#define STAGE_BYTES (4*128*RSB)       // Ah,Al,Bh,Bl tiles per stage = 73728
#define SA_HI 0
#define SA_LO 18432
#define SB_HI 36864
#define SB_LO 55296
#define GEMM_SMEM (2*STAGE_BYTES)     // 147456

__global__ __launch_bounds__(256, 1) void gemm_tc(
        const __nv_bfloat16* __restrict__ Ah, const __nv_bfloat16* __restrict__ Al,
        const __nv_bfloat16* __restrict__ Bh, const __nv_bfloat16* __restrict__ Bl,
        const float* __restrict__ bias, const float* __restrict__ R,
        float* __restrict__ C, int N, int K, int relu)
{
    extern __shared__ char smem[];
    const uint32_t sb = smem_to_u32(smem);
    const int tid = threadIdx.x, lane = tid & 31, wid = tid >> 5;
    const int wm = wid & 1, wn = wid >> 1;
    const int m0 = blockIdx.y * 128, n0 = blockIdx.x * 128;

    float acc[4][4][4];
#pragma unroll
    for (int i = 0; i < 4; i++)
#pragma unroll
        for (int j = 0; j < 4; j++)
#pragma unroll
            for (int q = 0; q < 4; q++) acc[i][j][q] = 0.f;

    const int nch = K >> 6;

    // stage fill: 1024 16B-vectors per tile, 4 tiles, 256 threads -> 16 cp.async/thread
    auto issue_stage = [&](int ch, int stg) {
        const int k0 = ch << 6;
        const uint32_t base = sb + stg * STAGE_BYTES;
#pragma unroll
        for (int i = tid; i < 1024; i += 256) {
            int r = i >> 3, c = i & 7;
            uint32_t doff = r * RSB + c * 16;
            size_t aoff = (size_t)(m0 + r) * K + k0 + c * 8;
            size_t boff = (size_t)(n0 + r) * K + k0 + c * 8;
            cpasync16(base + SA_HI + doff, Ah + aoff);
            cpasync16(base + SA_LO + doff, Al + aoff);
            cpasync16(base + SB_HI + doff, Bh + boff);
            cpasync16(base + SB_LO + doff, Bl + boff);
        }
        cpcommit();
    };

    issue_stage(0, 0);

    // ldmatrix per-lane address bases (within a tile)
    const uint32_t aAddr = (uint32_t)((wm*64 + (lane & 15)) * RSB + (lane >> 4) * 16);
    const uint32_t bAddr = (uint32_t)((wn*32 + (lane & 7) + ((lane >> 4) & 1) * 8) * RSB
                                      + ((lane >> 3) & 1) * 16);

    for (int ch = 0; ch < nch; ch++) {
        cpwait0();
        __syncthreads();
        if (ch + 1 < nch) issue_stage(ch + 1, (ch + 1) & 1);
        const uint32_t stg = sb + (ch & 1) * STAGE_BYTES;
#pragma unroll
        for (int ks = 0; ks < 4; ks++) {
            uint32_t ah[4][4], al[4][4], bh[2][4], bl[2][4];
#pragma unroll
            for (int ma = 0; ma < 4; ma++) {
                uint32_t ad = stg + SA_HI + aAddr + ma * (16 * RSB) + ks * 32;
                ldsm4(ah[ma][0], ah[ma][1], ah[ma][2], ah[ma][3], ad);
                ldsm4(al[ma][0], al[ma][1], al[ma][2], al[ma][3], ad + (SA_LO - SA_HI));
            }
#pragma unroll
            for (int nb = 0; nb < 2; nb++) {
                uint32_t bd = stg + SB_HI + bAddr + nb * (16 * RSB) + ks * 32;
                ldsm4(bh[nb][0], bh[nb][1], bh[nb][2], bh[nb][3], bd);
                ldsm4(bl[nb][0], bl[nb][1], bl[nb][2], bl[nb][3], bd + (SB_LO - SB_HI));
            }
#pragma unroll
            for (int ma = 0; ma < 4; ma++)
#pragma unroll
                for (int na = 0; na < 4; na++) {
                    const uint32_t bhp[2] = { bh[na >> 1][(na & 1) * 2],
                                              bh[na >> 1][(na & 1) * 2 + 1] };
                    const uint32_t blp[2] = { bl[na >> 1][(na & 1) * 2],
                                              bl[na >> 1][(na & 1) * 2 + 1] };
                    mma16816(acc[ma][na], ah[ma], bhp);
                    mma16816(acc[ma][na], ah[ma], blp);
                    mma16816(acc[ma][na], al[ma], bhp);
                }
        }
    }

    // epilogue: m16n8 fragment layout -> global, fused bias/R/relu
    const int g  = lane >> 2;
    const int qc = (lane & 3) * 2;
#pragma unroll
    for (int ma = 0; ma < 4; ma++) {
        const int row0 = m0 + wm*64 + ma*16 + g;
        const int row1 = row0 + 8;
#pragma unroll
        for (int na = 0; na < 4; na++) {
            const int col = n0 + wn*32 + na*8 + qc;
            const float b0 = bias[col], b1 = bias[col + 1];
            float v00 = acc[ma][na][0] + b0, v01 = acc[ma][na][1] + b1;
            float v10 = acc[ma][na][2] + b0, v11 = acc[ma][na][3] + b1;
            if (R) {
                float2 r0 = *(const float2*)&R[(size_t)row0 * N + col];
                float2 r1 = *(const float2*)&R[(size_t)row1 * N + col];
                v00 += r0.x; v01 += r0.y; v10 += r1.x; v11 += r1.y;
            }
            if (relu) {
                v00 = fmaxf(v00, 0.f); v01 = fmaxf(v01, 0.f);
                v10 = fmaxf(v10, 0.f); v11 = fmaxf(v11, 0.f);
            }
            *(float2*)&C[(size_t)row0 * N + col] = make_float2(v00, v01);
            *(float2*)&C[(size_t)row1 * N + col] = make_float2(v10, v11);
        }
    }
}

// ---------------- fused flash attention (fp32) -------------------------------
__device__ __forceinline__ int ksw(int r, int c) { return r*64 + (c ^ (r & 31)); }

__global__ __launch_bounds__(256)
void attn_kernel(const float* __restrict__ Qg, const float* __restrict__ Kg,
                 const float* __restrict__ Vg, float* __restrict__ Og,
                 const int* __restrict__ mask_ptr)
{
    __shared__ float Qs[64*64];
    __shared__ float Ks[64*64];
    __shared__ float Vs[64*64];

    const int q0 = blockIdx.x * 64;
    const int h  = blockIdx.y;
    const int b  = blockIdx.z;
    const int tid = threadIdx.x;
    const int tx = tid & 15, ty = tid >> 4;
    const int mask_lim = mask_ptr ? *mask_ptr : SEQ;

    const float* Qb = Qg + (size_t)b*SEQ*DIM + (size_t)h*DK;
    const float* Kb = Kg + (size_t)b*SEQ*DIM + (size_t)h*DK;
    const float* Vb = Vg + (size_t)b*SEQ*DIM + (size_t)h*DK;

    for (int e = tid; e < 4096; e += 256) {
        int r = e >> 6, c = e & 63;
        Qs[r*64+c] = Qb[(size_t)(q0+r)*DIM + c];
    }

    float m_i[4], l_i[4], o[4][4];
#pragma unroll
    for (int i = 0; i < 4; i++) {
        m_i[i] = -1e30f; l_i[i] = 0.f;
#pragma unroll
        for (int j = 0; j < 4; j++) o[i][j] = 0.f;
    }

    for (int t0 = 0; t0 < mask_lim; t0 += 64) {
        __syncthreads();
        for (int e = tid; e < 4096; e += 256) {
            int r = e >> 6, c = e & 63;
            Ks[ksw(r,c)] = Kb[(size_t)(t0+r)*DIM + c];
            Vs[r*64+c]   = Vb[(size_t)(t0+r)*DIM + c];
        }
        __syncthreads();

        float s[4][4];
#pragma unroll
        for (int i = 0; i < 4; i++)
#pragma unroll
            for (int j = 0; j < 4; j++) s[i][j] = 0.f;

        for (int kk = 0; kk < 64; kk++) {
            float qv[4], kv[4];
#pragma unroll
            for (int i = 0; i < 4; i++) qv[i] = Qs[(ty*4+i)*64 + kk];
#pragma unroll
            for (int j = 0; j < 4; j++) kv[j] = Ks[ksw(tx*4+j, kk)];
#pragma unroll
            for (int i = 0; i < 4; i++)
#pragma unroll
                for (int j = 0; j < 4; j++) s[i][j] += qv[i]*kv[j];
        }

#pragma unroll
        for (int i = 0; i < 4; i++) {
            float mt = -1e30f;
#pragma unroll
            for (int j = 0; j < 4; j++) {
                int col = t0 + tx*4 + j;
                float v = s[i][j] * 0.125f;
                if (col >= mask_lim) v = -1e30f;
                s[i][j] = v;
                mt = fmaxf(mt, v);
            }
#pragma unroll
            for (int off = 8; off; off >>= 1)
                mt = fmaxf(mt, __shfl_xor_sync(0xffffffffu, mt, off, 16));
            float mnew = fmaxf(m_i[i], mt);
            float corr = __expf(m_i[i] - mnew);
            l_i[i] *= corr;
#pragma unroll
            for (int j = 0; j < 4; j++) o[i][j] *= corr;
            float rs = 0.f;
#pragma unroll
            for (int j = 0; j < 4; j++) {
                float p = __expf(s[i][j] - mnew);
                s[i][j] = p; rs += p;
            }
#pragma unroll
            for (int off = 8; off; off >>= 1)
                rs += __shfl_xor_sync(0xffffffffu, rs, off, 16);
            l_i[i] += rs; m_i[i] = mnew;
        }

        __syncthreads();
#pragma unroll
        for (int i = 0; i < 4; i++)
#pragma unroll
            for (int j = 0; j < 4; j++)
                Ks[ksw(ty*4+i, tx*4+j)] = s[i][j];
        __syncthreads();

        for (int t = 0; t < 64; t++) {
            float pv[4], vv[4];
#pragma unroll
            for (int i = 0; i < 4; i++) pv[i] = Ks[ksw(ty*4+i, t)];
#pragma unroll
            for (int j = 0; j < 4; j++) vv[j] = Vs[t*64 + tx*4+j];
#pragma unroll
            for (int i = 0; i < 4; i++)
#pragma unroll
                for (int j = 0; j < 4; j++) o[i][j] += pv[i]*vv[j];
        }
    }

#pragma unroll
    for (int i = 0; i < 4; i++) {
        float inv = 1.f / l_i[i];
        int row = q0 + ty*4 + i;
#pragma unroll
        for (int j = 0; j < 4; j++)
            Og[(size_t)(b*SEQ + row)*DIM + h*DK + tx*4 + j] = o[i][j]*inv;
    }
}

// ---------------- BatchNorm1d: stats over (b,d) per s ------------------------
__global__ __launch_bounds__(256)
void bn_kernel(float* __restrict__ X, const float* __restrict__ g,
               const float* __restrict__ be)
{
    const int s = blockIdx.x;
    const int tid = threadIdx.x;
    float v[8];
    float sum = 0.f, sq = 0.f;
#pragma unroll
    for (int r = 0; r < 8; r++) {
        int idx = r*256 + tid;
        int b = idx >> 10, d = idx & 1023;
        float x = X[(size_t)(b*SEQ + s)*DIM + d];
        v[r] = x; sum += x; sq += x*x;
    }
#pragma unroll
    for (int off = 16; off; off >>= 1) {
        sum += __shfl_xor_sync(0xffffffffu, sum, off);
        sq  += __shfl_xor_sync(0xffffffffu, sq,  off);
    }
    __shared__ float ssum[8], ssq[8];
    if ((tid & 31) == 0) { ssum[tid>>5] = sum; ssq[tid>>5] = sq; }
    __syncthreads();
    sum = 0.f; sq = 0.f;
#pragma unroll
    for (int w = 0; w < 8; w++) { sum += ssum[w]; sq += ssq[w]; }
    const float mean = sum * (1.f/2048.f);
    const float var  = sq  * (1.f/2048.f) - mean*mean;
    const float inv  = rsqrtf(var + 1e-5f);
    const float sc   = g[s] * inv;
    const float sh   = be[s] - mean * sc;
#pragma unroll
    for (int r = 0; r < 8; r++) {
        int idx = r*256 + tid;
        int b = idx >> 10, d = idx & 1023;
        X[(size_t)(b*SEQ + s)*DIM + d] = v[r]*sc + sh;
    }
}

// ---------------- host orchestration ----------------------------------------
extern "C" void kernel_launch(void* const* d_in, const int* in_sizes, int n_in,
                              void* d_out, int out_size)
{
    const float* x   = (const float*)d_in[0];
    const float* Wq1 = (const float*)d_in[1];
    const float* bq1 = (const float*)d_in[2];
    const float* Wk1 = (const float*)d_in[3];
    const float* bk1 = (const float*)d_in[4];
    const float* Wv1 = (const float*)d_in[5];
    const float* bv1 = (const float*)d_in[6];
    const float* Wo1 = (const float*)d_in[7];
    const float* bo1 = (const float*)d_in[8];
    const float* Wq2 = (const float*)d_in[9];
    const float* bq2 = (const float*)d_in[10];
    const float* Wk2 = (const float*)d_in[11];
    const float* bk2 = (const float*)d_in[12];
    const float* Wv2 = (const float*)d_in[13];
    const float* bv2 = (const float*)d_in[14];
    const float* Wo2 = (const float*)d_in[15];
    const float* bo2 = (const float*)d_in[16];
    const float* g1  = (const float*)d_in[17];
    const float* be1 = (const float*)d_in[18];
    const float* g2  = (const float*)d_in[19];
    const float* be2 = (const float*)d_in[20];
    const float* g3  = (const float*)d_in[21];
    const float* be3 = (const float*)d_in[22];
    const float* W1  = (const float*)d_in[23];
    const float* bf1 = (const float*)d_in[24];
    const float* W2  = (const float*)d_in[25];
    const float* bf2 = (const float*)d_in[26];
    const int*   msk = (const int*)d_in[27];

    float *X, *X1, *Y, *Q, *K, *V, *O, *Hid;
    __nv_bfloat16 *Whi, *Wlo, *Ahi, *Alo;
    cudaGetSymbolAddress((void**)&X,   g_X);
    cudaGetSymbolAddress((void**)&X1,  g_X1);
    cudaGetSymbolAddress((void**)&Y,   g_Yb);
    cudaGetSymbolAddress((void**)&Q,   g_Qb);
    cudaGetSymbolAddress((void**)&K,   g_Kb);
    cudaGetSymbolAddress((void**)&V,   g_Vb);
    cudaGetSymbolAddress((void**)&O,   g_Ob);
    cudaGetSymbolAddress((void**)&Hid, g_Hid);
    cudaGetSymbolAddress((void**)&Whi, g_Whi);
    cudaGetSymbolAddress((void**)&Wlo, g_Wlo);
    cudaGetSymbolAddress((void**)&Ahi, g_Ahi);
    cudaGetSymbolAddress((void**)&Alo, g_Alo);

    cudaFuncSetAttribute(gemm_tc, cudaFuncAttributeMaxDynamicSharedMemorySize, GEMM_SMEM);

    const size_t bytesD = (size_t)MROWS * DIM * sizeof(float);
    cudaMemcpyAsync(X, x, bytesD, cudaMemcpyDeviceToDevice);

    // ---- weight transpose + split (all layers) ----
    {
        dim3 b(256);
        dim3 gQ(32, 32, NL);                 // K=1024, N=1024
        size_t sQKV = (size_t)NH * DIM * DK; // 1M per layer
        wsplit_t<<<gQ, b>>>(Wq1, Whi, Wlo, 1024, 1024, sQKV, OFF_Q1, 1);
        wsplit_t<<<gQ, b>>>(Wk1, Whi, Wlo, 1024, 1024, sQKV, OFF_K1, 1);
        wsplit_t<<<gQ, b>>>(Wv1, Whi, Wlo, 1024, 1024, sQKV, OFF_V1, 1);
        wsplit_t<<<gQ, b>>>(Wo1, Whi, Wlo, 1024, 1024, (size_t)DIM*DIM, OFF_O1, 0);
        wsplit_t<<<gQ, b>>>(Wq2, Whi, Wlo, 1024, 1024, sQKV, OFF_Q2, 1);
        wsplit_t<<<gQ, b>>>(Wk2, Whi, Wlo, 1024, 1024, sQKV, OFF_K2, 1);
        wsplit_t<<<gQ, b>>>(Wv2, Whi, Wlo, 1024, 1024, sQKV, OFF_V2, 1);
        wsplit_t<<<gQ, b>>>(Wo2, Whi, Wlo, 1024, 1024, (size_t)DIM*DIM, OFF_O2, 0);
        wsplit_t<<<dim3(32, 128, NL), b>>>(W1, Whi, Wlo, 1024, 4096, (size_t)DIM*FF, OFF_W1, 0);
        wsplit_t<<<dim3(128, 32, NL), b>>>(W2, Whi, Wlo, 4096, 1024, (size_t)FF*DIM, OFF_W2, 0);
    }

    const int n4D = MROWS * DIM / 4;
    const int n4F = MROWS * FF  / 4;
    dim3 gGD(DIM/128, MROWS/128);      // (8,16)  for N=1024
    dim3 gGF(FF/128,  MROWS/128);      // (32,16) for N=4096
    dim3 gA(SEQ/64, NH, NB);

    for (int l = 0; l < NL; l++) {
        const __nv_bfloat16* WH = Whi + (size_t)l * LAYER_W;
        const __nv_bfloat16* WL = Wlo + (size_t)l * LAYER_W;
        const size_t bO  = (size_t)l * NH * DK;
        const size_t dO  = (size_t)l * DIM;
        const size_t f1O = (size_t)l * FF;

        // ---- masked self-attention ----
        split_f32<<<n4D/256, 256>>>(X, Ahi, Alo, n4D);
        gemm_tc<<<gGD, 256, GEMM_SMEM>>>(Ahi, Alo, WH+OFF_Q1, WL+OFF_Q1, bq1+bO, nullptr, Q, DIM, DIM, 0);
        gemm_tc<<<gGD, 256, GEMM_SMEM>>>(Ahi, Alo, WH+OFF_K1, WL+OFF_K1, bk1+bO, nullptr, K, DIM, DIM, 0);
        gemm_tc<<<gGD, 256, GEMM_SMEM>>>(Ahi, Alo, WH+OFF_V1, WL+OFF_V1, bv1+bO, nullptr, V, DIM, DIM, 0);
        attn_kernel<<<gA, 256>>>(Q, K, V, O, msk);
        split_f32<<<n4D/256, 256>>>(O, Ahi, Alo, n4D);
        gemm_tc<<<gGD, 256, GEMM_SMEM>>>(Ahi, Alo, WH+OFF_O1, WL+OFF_O1, bo1+dO, X, X1, DIM, DIM, 0);
        bn_kernel<<<SEQ, 256>>>(X1, g1+dO, be1+dO);

        // ---- second (unmasked) attention; residual from block input X ----
        split_f32<<<n4D/256, 256>>>(X1, Ahi, Alo, n4D);
        gemm_tc<<<gGD, 256, GEMM_SMEM>>>(Ahi, Alo, WH+OFF_Q2, WL+OFF_Q2, bq2+bO, nullptr, Q, DIM, DIM, 0);
        gemm_tc<<<gGD, 256, GEMM_SMEM>>>(Ahi, Alo, WH+OFF_K2, WL+OFF_K2, bk2+bO, nullptr, K, DIM, DIM, 0);
        gemm_tc<<<gGD, 256, GEMM_SMEM>>>(Ahi, Alo, WH+OFF_V2, WL+OFF_V2, bv2+bO, nullptr, V, DIM, DIM, 0);
        attn_kernel<<<gA, 256>>>(Q, K, V, O, nullptr);
        split_f32<<<n4D/256, 256>>>(O, Ahi, Alo, n4D);
        gemm_tc<<<gGD, 256, GEMM_SMEM>>>(Ahi, Alo, WH+OFF_O2, WL+OFF_O2, bo2+dO, X, Y, DIM, DIM, 0);
        bn_kernel<<<SEQ, 256>>>(Y, g2+dO, be2+dO);

        // ---- FFN; residual from X1 ----
        split_f32<<<n4D/256, 256>>>(Y, Ahi, Alo, n4D);
        gemm_tc<<<gGF, 256, GEMM_SMEM>>>(Ahi, Alo, WH+OFF_W1, WL+OFF_W1, bf1+f1O, nullptr, Hid, FF, DIM, 1);
        split_f32<<<n4F/256, 256>>>(Hid, Ahi, Alo, n4F);
        gemm_tc<<<gGD, 256, GEMM_SMEM>>>(Ahi, Alo, WH+OFF_W2, WL+OFF_W2, bf2+dO, X1, X, DIM, FF, 0);
        bn_kernel<<<SEQ, 256>>>(X, g3+dO, be3+dO);
    }

    cudaMemcpyAsync(d_out, X, bytesD, cudaMemcpyDeviceToDevice);
}

// round 4
// speedup vs baseline: 4.0887x; 1.7649x over previous
#include <cuda_runtime.h>
#include <cuda_bf16.h>
#include <cstdint>

#define NB  2
#define SEQ 1024
#define DIM 1024
#define NH  16
#define DK  64
#define FF  4096
#define NL  4
#define MROWS (NB*SEQ)   // 2048

// ---------------- PTX helpers (baseline sm_103 — NO arch-feature suffix) -----
__device__ __forceinline__ uint32_t smem_to_u32(const void* p) {
    uint32_t a;
    asm("{ .reg .u64 t; cvta.to.shared.u64 t, %1; cvt.u32.u64 %0, t; }" : "=r"(a) : "l"(p));
    return a;
}
__device__ __forceinline__ void cpasync16(uint32_t dst, const void* src) {
    asm volatile("cp.async.cg.shared.global [%0], [%1], 16;"
                 :: "r"(dst), "l"(__cvta_generic_to_global(src)) : "memory");
}
__device__ __forceinline__ void cpcommit() { asm volatile("cp.async.commit_group;" ::: "memory"); }
__device__ __forceinline__ void cpwait0()  { asm volatile("cp.async.wait_group 0;" ::: "memory"); }
__device__ __forceinline__ void cpwait1()  { asm volatile("cp.async.wait_group 1;" ::: "memory"); }

__device__ __forceinline__ void ldsm4(uint32_t& r0, uint32_t& r1, uint32_t& r2, uint32_t& r3,
                                      uint32_t a) {
    asm volatile("ldmatrix.sync.aligned.m8n8.x4.shared.b16 {%0,%1,%2,%3}, [%4];"
                 : "=r"(r0), "=r"(r1), "=r"(r2), "=r"(r3) : "r"(a));
}
__device__ __forceinline__ void ldsm4t(uint32_t& r0, uint32_t& r1, uint32_t& r2, uint32_t& r3,
                                       uint32_t a) {
    asm volatile("ldmatrix.sync.aligned.m8n8.x4.trans.shared.b16 {%0,%1,%2,%3}, [%4];"
                 : "=r"(r0), "=r"(r1), "=r"(r2), "=r"(r3) : "r"(a));
}
__device__ __forceinline__ void mma16816(float* d, const uint32_t* a, const uint32_t* b) {
    asm volatile("mma.sync.aligned.m16n8k16.row.col.f32.bf16.bf16.f32 "
                 "{%0,%1,%2,%3}, {%4,%5,%6,%7}, {%8,%9}, {%0,%1,%2,%3};"
                 : "+f"(d[0]), "+f"(d[1]), "+f"(d[2]), "+f"(d[3])
                 : "r"(a[0]), "r"(a[1]), "r"(a[2]), "r"(a[3]), "r"(b[0]), "r"(b[1]));
}
__device__ __forceinline__ uint32_t packbf(float a, float b) {
    __nv_bfloat16 ha = __float2bfloat16(a), hb = __float2bfloat16(b);
    return (uint32_t)__bfloat16_as_ushort(ha) | ((uint32_t)__bfloat16_as_ushort(hb) << 16);
}

// ---------------- scratch (static device memory) -----------------------------
__device__ float g_X  [MROWS*DIM];
__device__ float g_X1 [MROWS*DIM];
__device__ float g_Yb [MROWS*DIM];
__device__ __nv_bfloat16 g_Xhi [MROWS*DIM], g_Xlo [MROWS*DIM];
__device__ __nv_bfloat16 g_X1hi[MROWS*DIM], g_X1lo[MROWS*DIM];
__device__ __nv_bfloat16 g_Yhi [MROWS*DIM], g_Ylo [MROWS*DIM];
__device__ __nv_bfloat16 g_Qhi [MROWS*DIM], g_Qlo [MROWS*DIM];
__device__ __nv_bfloat16 g_Khi [MROWS*DIM], g_Klo [MROWS*DIM];
__device__ __nv_bfloat16 g_Vhi [MROWS*DIM], g_Vlo [MROWS*DIM];
__device__ __nv_bfloat16 g_Ohi [MROWS*DIM], g_Olo [MROWS*DIM];
__device__ __nv_bfloat16 g_Hhi [MROWS*FF],  g_Hlo [MROWS*FF];
// split-bf16 weights, transposed to [N][K], all layers
__device__ __nv_bfloat16 g_Whi[64u*1024*1024];
__device__ __nv_bfloat16 g_Wlo[64u*1024*1024];

#define LAYER_W  (16u*1024*1024)
#define OFF_Q1   (0u)
#define OFF_K1   (1u*1024*1024)
#define OFF_V1   (2u*1024*1024)
#define OFF_O1   (3u*1024*1024)
#define OFF_Q2   (4u*1024*1024)
#define OFF_K2   (5u*1024*1024)
#define OFF_V2   (6u*1024*1024)
#define OFF_O2   (7u*1024*1024)
#define OFF_W1   (8u*1024*1024)
#define OFF_W2   (12u*1024*1024)

// ---------------- activation split: fp32 -> (hi, lo) bf16 --------------------
__global__ __launch_bounds__(256) void split_f32(const float* __restrict__ x,
        __nv_bfloat16* __restrict__ h, __nv_bfloat16* __restrict__ l, int n4)
{
    int i = blockIdx.x * 256 + threadIdx.x;
    if (i >= n4) return;
    float4 v = ((const float4*)x)[i];
    __nv_bfloat16 h0 = __float2bfloat16(v.x), h1 = __float2bfloat16(v.y);
    __nv_bfloat16 h2 = __float2bfloat16(v.z), h3 = __float2bfloat16(v.w);
    uint2 hp, lp;
    hp.x = packbf(v.x, v.y); hp.y = packbf(v.z, v.w);
    lp.x = packbf(v.x - __bfloat162float(h0), v.y - __bfloat162float(h1));
    lp.y = packbf(v.z - __bfloat162float(h2), v.w - __bfloat162float(h3));
    ((uint2*)h)[i] = hp;
    ((uint2*)l)[i] = lp;
}

// ------------- weight transpose+split: W[K,N](or head) -> Wt[N,K] hi/lo ------
__global__ __launch_bounds__(256) void wsplit_t(const float* __restrict__ W,
        __nv_bfloat16* __restrict__ oh, __nv_bfloat16* __restrict__ ol,
        int K, int N, size_t inLayerStride, size_t outOff, int headMode)
{
    __shared__ float t[32][33];
    int tx = threadIdx.x & 31, ty = threadIdx.x >> 5;
    int k0 = blockIdx.x * 32, n0 = blockIdx.y * 32;
    const float* Win = W + (size_t)blockIdx.z * inLayerStride;
    size_t ob = (size_t)blockIdx.z * LAYER_W + outOff;
#pragma unroll
    for (int i = 0; i < 4; i++) {
        int k = k0 + ty + 8*i, n = n0 + tx;
        size_t idx = headMode ? ((size_t)(n >> 6) * K * 64 + (size_t)k * 64 + (n & 63))
                              : ((size_t)k * N + n);
        t[ty + 8*i][tx] = Win[idx];
    }
    __syncthreads();
#pragma unroll
    for (int i = 0; i < 4; i++) {
        int n = n0 + ty + 8*i, k = k0 + tx;
        float v = t[tx][ty + 8*i];
        __nv_bfloat16 hi = __float2bfloat16(v);
        oh[ob + (size_t)n * K + k] = hi;
        ol[ob + (size_t)n * K + k] = __float2bfloat16(v - __bfloat162float(hi));
    }
}

// ---------------- split-bf16 HMMA GEMM ---------------------------------------
// C = A(2048xK) @ B^T + bias (+R) (+relu); optional split-bf16 output (Chi/Clo)
#define RSB 144
#define STAGE_BYTES (4*128*RSB)
#define SA_HI 0
#define SA_LO 18432
#define SB_HI 36864
#define SB_LO 55296
#define GEMM_SMEM (2*STAGE_BYTES)

__global__ __launch_bounds__(256, 1) void gemm_tc(
        const __nv_bfloat16* __restrict__ Ah, const __nv_bfloat16* __restrict__ Al,
        const __nv_bfloat16* __restrict__ Bh, const __nv_bfloat16* __restrict__ Bl,
        const float* __restrict__ bias, const float* __restrict__ R,
        float* __restrict__ C,
        __nv_bfloat16* __restrict__ Chi, __nv_bfloat16* __restrict__ Clo,
        int N, int K, int relu)
{
    extern __shared__ char smem[];
    const uint32_t sb = smem_to_u32(smem);
    const int tid = threadIdx.x, lane = tid & 31, wid = tid >> 5;
    const int wm = wid & 1, wn = wid >> 1;
    const int m0 = blockIdx.y * 128, n0 = blockIdx.x * 128;

    float acc[4][4][4];
#pragma unroll
    for (int i = 0; i < 4; i++)
#pragma unroll
        for (int j = 0; j < 4; j++)
#pragma unroll
            for (int q = 0; q < 4; q++) acc[i][j][q] = 0.f;

    const int nch = K >> 6;
    auto issue_stage = [&](int ch, int stg) {
        const int k0 = ch << 6;
        const uint32_t base = sb + stg * STAGE_BYTES;
#pragma unroll
        for (int i = tid; i < 1024; i += 256) {
            int r = i >> 3, c = i & 7;
            uint32_t doff = r * RSB + c * 16;
            size_t aoff = (size_t)(m0 + r) * K + k0 + c * 8;
            size_t boff = (size_t)(n0 + r) * K + k0 + c * 8;
            cpasync16(base + SA_HI + doff, Ah + aoff);
            cpasync16(base + SA_LO + doff, Al + aoff);
            cpasync16(base + SB_HI + doff, Bh + boff);
            cpasync16(base + SB_LO + doff, Bl + boff);
        }
        cpcommit();
    };

    issue_stage(0, 0);

    const uint32_t aAddr = (uint32_t)((wm*64 + (lane & 15)) * RSB + (lane >> 4) * 16);
    const uint32_t bAddr = (uint32_t)((wn*32 + (lane & 7) + ((lane >> 4) & 1) * 8) * RSB
                                      + ((lane >> 3) & 1) * 16);

    for (int ch = 0; ch < nch; ch++) {
        cpwait0();
        __syncthreads();
        if (ch + 1 < nch) issue_stage(ch + 1, (ch + 1) & 1);
        const uint32_t stg = sb + (ch & 1) * STAGE_BYTES;
#pragma unroll
        for (int ks = 0; ks < 4; ks++) {
            uint32_t ah[4][4], al[4][4], bh[2][4], bl[2][4];
#pragma unroll
            for (int ma = 0; ma < 4; ma++) {
                uint32_t ad = stg + SA_HI + aAddr + ma * (16 * RSB) + ks * 32;
                ldsm4(ah[ma][0], ah[ma][1], ah[ma][2], ah[ma][3], ad);
                ldsm4(al[ma][0], al[ma][1], al[ma][2], al[ma][3], ad + (SA_LO - SA_HI));
            }
#pragma unroll
            for (int nb = 0; nb < 2; nb++) {
                uint32_t bd = stg + SB_HI + bAddr + nb * (16 * RSB) + ks * 32;
                ldsm4(bh[nb][0], bh[nb][1], bh[nb][2], bh[nb][3], bd);
                ldsm4(bl[nb][0], bl[nb][1], bl[nb][2], bl[nb][3], bd + (SB_LO - SB_HI));
            }
#pragma unroll
            for (int ma = 0; ma < 4; ma++)
#pragma unroll
                for (int na = 0; na < 4; na++) {
                    const uint32_t bhp[2] = { bh[na >> 1][(na & 1) * 2],
                                              bh[na >> 1][(na & 1) * 2 + 1] };
                    const uint32_t blp[2] = { bl[na >> 1][(na & 1) * 2],
                                              bl[na >> 1][(na & 1) * 2 + 1] };
                    mma16816(acc[ma][na], ah[ma], bhp);
                    mma16816(acc[ma][na], ah[ma], blp);
                    mma16816(acc[ma][na], al[ma], bhp);
                }
        }
    }

    const int g  = lane >> 2;
    const int qc = (lane & 3) * 2;
#pragma unroll
    for (int ma = 0; ma < 4; ma++) {
        const int row0 = m0 + wm*64 + ma*16 + g;
        const int row1 = row0 + 8;
#pragma unroll
        for (int na = 0; na < 4; na++) {
            const int col = n0 + wn*32 + na*8 + qc;
            const float b0 = bias[col], b1 = bias[col + 1];
            float v00 = acc[ma][na][0] + b0, v01 = acc[ma][na][1] + b1;
            float v10 = acc[ma][na][2] + b0, v11 = acc[ma][na][3] + b1;
            if (R) {
                float2 r0 = *(const float2*)&R[(size_t)row0 * N + col];
                float2 r1 = *(const float2*)&R[(size_t)row1 * N + col];
                v00 += r0.x; v01 += r0.y; v10 += r1.x; v11 += r1.y;
            }
            if (relu) {
                v00 = fmaxf(v00, 0.f); v01 = fmaxf(v01, 0.f);
                v10 = fmaxf(v10, 0.f); v11 = fmaxf(v11, 0.f);
            }
            if (Chi) {
                float h00 = __bfloat162float(__float2bfloat16(v00));
                float h01 = __bfloat162float(__float2bfloat16(v01));
                float h10 = __bfloat162float(__float2bfloat16(v10));
                float h11 = __bfloat162float(__float2bfloat16(v11));
                *(uint32_t*)&Chi[(size_t)row0 * N + col] = packbf(v00, v01);
                *(uint32_t*)&Chi[(size_t)row1 * N + col] = packbf(v10, v11);
                *(uint32_t*)&Clo[(size_t)row0 * N + col] = packbf(v00 - h00, v01 - h01);
                *(uint32_t*)&Clo[(size_t)row1 * N + col] = packbf(v10 - h10, v11 - h11);
            } else {
                *(float2*)&C[(size_t)row0 * N + col] = make_float2(v00, v01);
                *(float2*)&C[(size_t)row1 * N + col] = make_float2(v10, v11);
            }
        }
    }
}

// ---------------- HMMA flash attention (split-bf16 everywhere) ---------------
// Q/K/V hi/lo in [token][h*64+d]; O written split to Ohi/Olo.
#define ARS 144
#define AQ_HI 0
#define AQ_LO 18432
#define AKV0  36864          // per-stage: Khi,Klo,Vhi,Vlo each 64*144=9216
#define AKV_STAGE 36864
#define ATT_SMEM (AKV0 + 2*AKV_STAGE)   // 110592

__global__ __launch_bounds__(256, 2) void attn_tc(
        const __nv_bfloat16* __restrict__ Qh, const __nv_bfloat16* __restrict__ Ql,
        const __nv_bfloat16* __restrict__ Kh, const __nv_bfloat16* __restrict__ Kl,
        const __nv_bfloat16* __restrict__ Vh, const __nv_bfloat16* __restrict__ Vl,
        __nv_bfloat16* __restrict__ Ohi, __nv_bfloat16* __restrict__ Olo,
        const int* __restrict__ mask_ptr)
{
    extern __shared__ char smem[];
    const uint32_t sb = smem_to_u32(smem);
    const int tid = threadIdx.x, lane = tid & 31, w = tid >> 5;
    const int q0 = blockIdx.x * 128, h = blockIdx.y, b = blockIdx.z;
    const int lim = mask_ptr ? *mask_ptr : SEQ;
    const size_t tokbase = (size_t)b * SEQ;
    const int colbase = h * DK;

    // Q load (128 rows x 64 cols, hi+lo)
    for (int i = tid; i < 1024; i += 256) {
        int r = i >> 3, c = i & 7;
        uint32_t qd = sb + r * ARS + c * 16;
        size_t gi = (tokbase + q0 + r) * DIM + colbase + c * 8;
        cpasync16(qd + AQ_HI, Qh + gi);
        cpasync16(qd + AQ_LO, Ql + gi);
    }
    auto ldkv = [&](int t, int stg) {
        uint32_t base = sb + AKV0 + stg * AKV_STAGE;
        for (int i = tid; i < 512; i += 256) {
            int r = i >> 3, c = i & 7;
            uint32_t off = r * ARS + c * 16;
            size_t gi = (tokbase + t * 64 + r) * DIM + colbase + c * 8;
            cpasync16(base + off,         Kh + gi);
            cpasync16(base + 9216 + off,  Kl + gi);
            cpasync16(base + 18432 + off, Vh + gi);
            cpasync16(base + 27648 + off, Vl + gi);
        }
        cpcommit();
    };
    ldkv(0, 0);

    const int nt = (lim + 63) >> 6;
    const int g = lane >> 2, qc = (lane & 3) * 2;
    const int wq = w * 16;

    float m[2] = {-1e30f, -1e30f}, l[2] = {0.f, 0.f};
    float o[8][4];
#pragma unroll
    for (int i = 0; i < 8; i++)
#pragma unroll
        for (int j = 0; j < 4; j++) o[i][j] = 0.f;

    for (int t = 0; t < nt; t++) {
        __syncthreads();
        if (t + 1 < nt) { ldkv(t + 1, (t + 1) & 1); cpwait1(); }
        else           { cpwait0(); }
        __syncthreads();
        const uint32_t kb = sb + AKV0 + (t & 1) * AKV_STAGE;

        // ---- scores S = Q K^T (split, 3 terms) ----
        float sc[8][4];
#pragma unroll
        for (int i = 0; i < 8; i++)
#pragma unroll
            for (int j = 0; j < 4; j++) sc[i][j] = 0.f;

#pragma unroll
        for (int ks = 0; ks < 4; ks++) {
            uint32_t qa = sb + (wq + (lane & 15)) * ARS + (lane >> 4) * 16 + ks * 32;
            uint32_t qhr[4], qlr[4];
            ldsm4(qhr[0], qhr[1], qhr[2], qhr[3], qa + AQ_HI);
            ldsm4(qlr[0], qlr[1], qlr[2], qlr[3], qa + AQ_LO);
#pragma unroll
            for (int p = 0; p < 4; p++) {
                uint32_t ka = kb + (p*16 + (lane & 7) + ((lane >> 4) & 1) * 8) * ARS
                              + ((lane >> 3) & 1) * 16 + ks * 32;
                uint32_t kh[4], kl[4];
                ldsm4(kh[0], kh[1], kh[2], kh[3], ka);
                ldsm4(kl[0], kl[1], kl[2], kl[3], ka + 9216);
                const uint32_t kh01[2] = {kh[0], kh[1]}, kh23[2] = {kh[2], kh[3]};
                const uint32_t kl01[2] = {kl[0], kl[1]}, kl23[2] = {kl[2], kl[3]};
                mma16816(sc[2*p],   qhr, kh01);
                mma16816(sc[2*p],   qhr, kl01);
                mma16816(sc[2*p],   qlr, kh01);
                mma16816(sc[2*p+1], qhr, kh23);
                mma16816(sc[2*p+1], qhr, kl23);
                mma16816(sc[2*p+1], qlr, kh23);
            }
        }

        // ---- scale + mask ----
        const int t0 = t * 64;
#pragma unroll
        for (int na = 0; na < 8; na++) {
            int c0 = t0 + na*8 + qc, c1 = c0 + 1;
#pragma unroll
            for (int j = 0; j < 2; j++) {
                float s0 = sc[na][2*j]   * 0.125f;
                float s1 = sc[na][2*j+1] * 0.125f;
                sc[na][2*j]   = (c0 < lim) ? s0 : -1e30f;
                sc[na][2*j+1] = (c1 < lim) ? s1 : -1e30f;
            }
        }

        // ---- online softmax (rows g, g+8) ----
#pragma unroll
        for (int j = 0; j < 2; j++) {
            float mx = -1e30f;
#pragma unroll
            for (int na = 0; na < 8; na++)
                mx = fmaxf(mx, fmaxf(sc[na][2*j], sc[na][2*j+1]));
            mx = fmaxf(mx, __shfl_xor_sync(0xffffffffu, mx, 1));
            mx = fmaxf(mx, __shfl_xor_sync(0xffffffffu, mx, 2));
            float mnew = fmaxf(m[j], mx);
            float corr = __expf(m[j] - mnew);
            l[j] *= corr;
            m[j] = mnew;
#pragma unroll
            for (int nd = 0; nd < 8; nd++) { o[nd][2*j] *= corr; o[nd][2*j+1] *= corr; }
            float sum = 0.f;
#pragma unroll
            for (int na = 0; na < 8; na++) {
                float p0 = __expf(sc[na][2*j]   - mnew);
                float p1 = __expf(sc[na][2*j+1] - mnew);
                sc[na][2*j] = p0; sc[na][2*j+1] = p1;
                sum += p0 + p1;
            }
            sum += __shfl_xor_sync(0xffffffffu, sum, 1);
            sum += __shfl_xor_sync(0xffffffffu, sum, 2);
            l[j] += sum;
        }

        // ---- O += P V (split, 3 terms); P -> A-frags in registers ----
#pragma unroll
        for (int kp = 0; kp < 4; kp++) {
            float p00 = sc[2*kp][0],   p01 = sc[2*kp][1];
            float p02 = sc[2*kp][2],   p03 = sc[2*kp][3];
            float p10 = sc[2*kp+1][0], p11 = sc[2*kp+1][1];
            float p12 = sc[2*kp+1][2], p13 = sc[2*kp+1][3];
            float h00 = __bfloat162float(__float2bfloat16(p00));
            float h01 = __bfloat162float(__float2bfloat16(p01));
            float h02 = __bfloat162float(__float2bfloat16(p02));
            float h03 = __bfloat162float(__float2bfloat16(p03));
            float h10 = __bfloat162float(__float2bfloat16(p10));
            float h11 = __bfloat162float(__float2bfloat16(p11));
            float h12 = __bfloat162float(__float2bfloat16(p12));
            float h13 = __bfloat162float(__float2bfloat16(p13));
            uint32_t aph[4] = { packbf(p00, p01), packbf(p02, p03),
                                packbf(p10, p11), packbf(p12, p13) };
            uint32_t apl[4] = { packbf(p00-h00, p01-h01), packbf(p02-h02, p03-h03),
                                packbf(p10-h10, p11-h11), packbf(p12-h12, p13-h13) };
#pragma unroll
            for (int vp = 0; vp < 4; vp++) {
                uint32_t va = kb + 18432 + (kp*16 + (lane & 15)) * ARS
                              + (vp*2 + (lane >> 4)) * 16;
                uint32_t vh[4], vl[4];
                ldsm4t(vh[0], vh[1], vh[2], vh[3], va);
                ldsm4t(vl[0], vl[1], vl[2], vl[3], va + 9216);
                const uint32_t vh01[2] = {vh[0], vh[1]}, vh23[2] = {vh[2], vh[3]};
                const uint32_t vl01[2] = {vl[0], vl[1]}, vl23[2] = {vl[2], vl[3]};
                mma16816(o[2*vp],   aph, vh01);
                mma16816(o[2*vp],   aph, vl01);
                mma16816(o[2*vp],   apl, vh01);
                mma16816(o[2*vp+1], aph, vh23);
                mma16816(o[2*vp+1], aph, vl23);
                mma16816(o[2*vp+1], apl, vh23);
            }
        }
    }

    // ---- epilogue: normalize, split, store ----
#pragma unroll
    for (int j = 0; j < 2; j++) {
        float inv = 1.f / l[j];
        int row = q0 + wq + g + j*8;
        size_t gb = (tokbase + row) * DIM + colbase;
#pragma unroll
        for (int nd = 0; nd < 8; nd++) {
            float v0 = o[nd][2*j] * inv, v1 = o[nd][2*j+1] * inv;
            float h0 = __bfloat162float(__float2bfloat16(v0));
            float h1 = __bfloat162float(__float2bfloat16(v1));
            *(uint32_t*)&Ohi[gb + nd*8 + qc] = packbf(v0, v1);
            *(uint32_t*)&Olo[gb + nd*8 + qc] = packbf(v0 - h0, v1 - h1);
        }
    }
}

// ---------------- BatchNorm1d + fused split output ---------------------------
__global__ __launch_bounds__(256)
void bn_kernel(float* __restrict__ X, const float* __restrict__ g,
               const float* __restrict__ be,
               __nv_bfloat16* __restrict__ Xh, __nv_bfloat16* __restrict__ Xl)
{
    const int s = blockIdx.x;
    const int tid = threadIdx.x;
    float v[8];
    float sum = 0.f, sq = 0.f;
#pragma unroll
    for (int r = 0; r < 8; r++) {
        int idx = r*256 + tid;
        int b = idx >> 10, d = idx & 1023;
        float x = X[(size_t)(b*SEQ + s)*DIM + d];
        v[r] = x; sum += x; sq += x*x;
    }
#pragma unroll
    for (int off = 16; off; off >>= 1) {
        sum += __shfl_xor_sync(0xffffffffu, sum, off);
        sq  += __shfl_xor_sync(0xffffffffu, sq,  off);
    }
    __shared__ float ssum[8], ssq[8];
    if ((tid & 31) == 0) { ssum[tid>>5] = sum; ssq[tid>>5] = sq; }
    __syncthreads();
    sum = 0.f; sq = 0.f;
#pragma unroll
    for (int w = 0; w < 8; w++) { sum += ssum[w]; sq += ssq[w]; }
    const float mean = sum * (1.f/2048.f);
    const float var  = sq  * (1.f/2048.f) - mean*mean;
    const float inv  = rsqrtf(var + 1e-5f);
    const float sc   = g[s] * inv;
    const float sh   = be[s] - mean * sc;
#pragma unroll
    for (int r = 0; r < 8; r++) {
        int idx = r*256 + tid;
        int b = idx >> 10, d = idx & 1023;
        size_t gi = (size_t)(b*SEQ + s)*DIM + d;
        float y = v[r]*sc + sh;
        X[gi] = y;
        __nv_bfloat16 hi = __float2bfloat16(y);
        Xh[gi] = hi;
        Xl[gi] = __float2bfloat16(y - __bfloat162float(hi));
    }
}

// ---------------- host orchestration ----------------------------------------
extern "C" void kernel_launch(void* const* d_in, const int* in_sizes, int n_in,
                              void* d_out, int out_size)
{
    const float* x   = (const float*)d_in[0];
    const float* Wq1 = (const float*)d_in[1];
    const float* bq1 = (const float*)d_in[2];
    const float* Wk1 = (const float*)d_in[3];
    const float* bk1 = (const float*)d_in[4];
    const float* Wv1 = (const float*)d_in[5];
    const float* bv1 = (const float*)d_in[6];
    const float* Wo1 = (const float*)d_in[7];
    const float* bo1 = (const float*)d_in[8];
    const float* Wq2 = (const float*)d_in[9];
    const float* bq2 = (const float*)d_in[10];
    const float* Wk2 = (const float*)d_in[11];
    const float* bk2 = (const float*)d_in[12];
    const float* Wv2 = (const float*)d_in[13];
    const float* bv2 = (const float*)d_in[14];
    const float* Wo2 = (const float*)d_in[15];
    const float* bo2 = (const float*)d_in[16];
    const float* g1  = (const float*)d_in[17];
    const float* be1 = (const float*)d_in[18];
    const float* g2  = (const float*)d_in[19];
    const float* be2 = (const float*)d_in[20];
    const float* g3  = (const float*)d_in[21];
    const float* be3 = (const float*)d_in[22];
    const float* W1  = (const float*)d_in[23];
    const float* bf1 = (const float*)d_in[24];
    const float* W2  = (const float*)d_in[25];
    const float* bf2 = (const float*)d_in[26];
    const int*   msk = (const int*)d_in[27];

    float *X, *X1, *Y;
    __nv_bfloat16 *Whi, *Wlo;
    __nv_bfloat16 *Xhi, *Xlo, *X1hi, *X1lo, *Yhi, *Ylo;
    __nv_bfloat16 *Qhi, *Qlo, *Khi, *Klo, *Vhi, *Vlo, *Ohi, *Olo, *Hhi, *Hlo;
    cudaGetSymbolAddress((void**)&X,    g_X);
    cudaGetSymbolAddress((void**)&X1,   g_X1);
    cudaGetSymbolAddress((void**)&Y,    g_Yb);
    cudaGetSymbolAddress((void**)&Whi,  g_Whi);
    cudaGetSymbolAddress((void**)&Wlo,  g_Wlo);
    cudaGetSymbolAddress((void**)&Xhi,  g_Xhi);  cudaGetSymbolAddress((void**)&Xlo,  g_Xlo);
    cudaGetSymbolAddress((void**)&X1hi, g_X1hi); cudaGetSymbolAddress((void**)&X1lo, g_X1lo);
    cudaGetSymbolAddress((void**)&Yhi,  g_Yhi);  cudaGetSymbolAddress((void**)&Ylo,  g_Ylo);
    cudaGetSymbolAddress((void**)&Qhi,  g_Qhi);  cudaGetSymbolAddress((void**)&Qlo,  g_Qlo);
    cudaGetSymbolAddress((void**)&Khi,  g_Khi);  cudaGetSymbolAddress((void**)&Klo,  g_Klo);
    cudaGetSymbolAddress((void**)&Vhi,  g_Vhi);  cudaGetSymbolAddress((void**)&Vlo,  g_Vlo);
    cudaGetSymbolAddress((void**)&Ohi,  g_Ohi);  cudaGetSymbolAddress((void**)&Olo,  g_Olo);
    cudaGetSymbolAddress((void**)&Hhi,  g_Hhi);  cudaGetSymbolAddress((void**)&Hlo,  g_Hlo);

    cudaFuncSetAttribute(gemm_tc, cudaFuncAttributeMaxDynamicSharedMemorySize, GEMM_SMEM);
    cudaFuncSetAttribute(attn_tc, cudaFuncAttributeMaxDynamicSharedMemorySize, ATT_SMEM);

    const size_t bytesD = (size_t)MROWS * DIM * sizeof(float);
    cudaMemcpyAsync(X, x, bytesD, cudaMemcpyDeviceToDevice);

    // ---- weight transpose + split (all layers) ----
    {
        dim3 b(256);
        dim3 gQ(32, 32, NL);
        size_t sQKV = (size_t)NH * DIM * DK;
        wsplit_t<<<gQ, b>>>(Wq1, Whi, Wlo, 1024, 1024, sQKV, OFF_Q1, 1);
        wsplit_t<<<gQ, b>>>(Wk1, Whi, Wlo, 1024, 1024, sQKV, OFF_K1, 1);
        wsplit_t<<<gQ, b>>>(Wv1, Whi, Wlo, 1024, 1024, sQKV, OFF_V1, 1);
        wsplit_t<<<gQ, b>>>(Wo1, Whi, Wlo, 1024, 1024, (size_t)DIM*DIM, OFF_O1, 0);
        wsplit_t<<<gQ, b>>>(Wq2, Whi, Wlo, 1024, 1024, sQKV, OFF_Q2, 1);
        wsplit_t<<<gQ, b>>>(Wk2, Whi, Wlo, 1024, 1024, sQKV, OFF_K2, 1);
        wsplit_t<<<gQ, b>>>(Wv2, Whi, Wlo, 1024, 1024, sQKV, OFF_V2, 1);
        wsplit_t<<<gQ, b>>>(Wo2, Whi, Wlo, 1024, 1024, (size_t)DIM*DIM, OFF_O2, 0);
        wsplit_t<<<dim3(32, 128, NL), b>>>(W1, Whi, Wlo, 1024, 4096, (size_t)DIM*FF, OFF_W1, 0);
        wsplit_t<<<dim3(128, 32, NL), b>>>(W2, Whi, Wlo, 4096, 1024, (size_t)FF*DIM, OFF_W2, 0);
    }

    const int n4D = MROWS * DIM / 4;
    split_f32<<<n4D/256, 256>>>(X, Xhi, Xlo, n4D);

    dim3 gGD(DIM/128, MROWS/128);
    dim3 gGF(FF/128,  MROWS/128);
    dim3 gA(SEQ/128, NH, NB);      // (8,16,2)

    for (int l = 0; l < NL; l++) {
        const __nv_bfloat16* WH = Whi + (size_t)l * LAYER_W;
        const __nv_bfloat16* WL = Wlo + (size_t)l * LAYER_W;
        const size_t bO  = (size_t)l * NH * DK;
        const size_t dO  = (size_t)l * DIM;
        const size_t f1O = (size_t)l * FF;

        // ---- masked self-attention ----
        gemm_tc<<<gGD, 256, GEMM_SMEM>>>(Xhi, Xlo, WH+OFF_Q1, WL+OFF_Q1, bq1+bO, nullptr, nullptr, Qhi, Qlo, DIM, DIM, 0);
        gemm_tc<<<gGD, 256, GEMM_SMEM>>>(Xhi, Xlo, WH+OFF_K1, WL+OFF_K1, bk1+bO, nullptr, nullptr, Khi, Klo, DIM, DIM, 0);
        gemm_tc<<<gGD, 256, GEMM_SMEM>>>(Xhi, Xlo, WH+OFF_V1, WL+OFF_V1, bv1+bO, nullptr, nullptr, Vhi, Vlo, DIM, DIM, 0);
        attn_tc<<<gA, 256, ATT_SMEM>>>(Qhi, Qlo, Khi, Klo, Vhi, Vlo, Ohi, Olo, msk);
        gemm_tc<<<gGD, 256, GEMM_SMEM>>>(Ohi, Olo, WH+OFF_O1, WL+OFF_O1, bo1+dO, X, X1, nullptr, nullptr, DIM, DIM, 0);
        bn_kernel<<<SEQ, 256>>>(X1, g1+dO, be1+dO, X1hi, X1lo);

        // ---- second (unmasked) attention; residual from block input X ----
        gemm_tc<<<gGD, 256, GEMM_SMEM>>>(X1hi, X1lo, WH+OFF_Q2, WL+OFF_Q2, bq2+bO, nullptr, nullptr, Qhi, Qlo, DIM, DIM, 0);
        gemm_tc<<<gGD, 256, GEMM_SMEM>>>(X1hi, X1lo, WH+OFF_K2, WL+OFF_K2, bk2+bO, nullptr, nullptr, Khi, Klo, DIM, DIM, 0);
        gemm_tc<<<gGD, 256, GEMM_SMEM>>>(X1hi, X1lo, WH+OFF_V2, WL+OFF_V2, bv2+bO, nullptr, nullptr, Vhi, Vlo, DIM, DIM, 0);
        attn_tc<<<gA, 256, ATT_SMEM>>>(Qhi, Qlo, Khi, Klo, Vhi, Vlo, Ohi, Olo, nullptr);
        gemm_tc<<<gGD, 256, GEMM_SMEM>>>(Ohi, Olo, WH+OFF_O2, WL+OFF_O2, bo2+dO, X, Y, nullptr, nullptr, DIM, DIM, 0);
        bn_kernel<<<SEQ, 256>>>(Y, g2+dO, be2+dO, Yhi, Ylo);

        // ---- FFN; residual from X1 ----
        gemm_tc<<<gGF, 256, GEMM_SMEM>>>(Yhi, Ylo, WH+OFF_W1, WL+OFF_W1, bf1+f1O, nullptr, nullptr, Hhi, Hlo, FF, DIM, 1);
        gemm_tc<<<gGD, 256, GEMM_SMEM>>>(Hhi, Hlo, WH+OFF_W2, WL+OFF_W2, bf2+dO, X1, X, nullptr, nullptr, DIM, FF, 0);
        bn_kernel<<<SEQ, 256>>>(X, g3+dO, be3+dO, Xhi, Xlo);
    }

    cudaMemcpyAsync(d_out, X, bytesD, cudaMemcpyDeviceToDevice);
}